// round 7
// baseline (speedup 1.0000x reference)
#include <cuda_runtime.h>
#include <cuda_bf16.h>
#include <cstdint>

// Problem constants
#define PB  16
#define PTV 128
#define PTH 64
#define PF  512
#define PH  512
#define PD  256
#define KDIM 512

// GEMM geometry: rows = [v (2048) ; h (1024)] = 3072 = 48 tiles of 64
// N = 256 = 4 tiles of 64. K = 512 = 32 iters of 16.
#define MTILES 48
#define KITERS 32

// ---------------------------------------------------------------------------
// Device scratch
// ---------------------------------------------------------------------------
// A fragments, per-lane packed for mma.sync m16n8k16 bf16:
//   [tile 48][kit 32][mfrag 4][hl 2][lane 32] : uint4 = regs {a01, a23, a45, a67}
__device__ uint4 g_Afrag[MTILES * KITERS * 4 * 2 * 32];
// B fragments: [mat 2][kit 32][nfrag 32][lane 32] : uint4 = {bhi01, bhi23, blo01, blo23}
__device__ uint4 g_Bfrag[2 * KITERS * 32 * 32];

__device__ float g_WvT[PB * PD * PTV];   // [b][d][t]
__device__ float g_Uhb[PB * PTH * PD];   // [b][s][d]

__device__ __forceinline__ float tanh_approx(float x) {
    float r; asm("tanh.approx.f32 %0, %1;" : "=f"(r) : "f"(x)); return r;
}
__device__ __forceinline__ uint32_t pack2(__nv_bfloat16 a, __nv_bfloat16 b) {
    return (uint32_t)__bfloat16_as_ushort(a) | ((uint32_t)__bfloat16_as_ushort(b) << 16);
}
__device__ __forceinline__ void split_bf16(float x, __nv_bfloat16& hi, __nv_bfloat16& lo) {
    hi = __float2bfloat16(x);
    lo = __float2bfloat16(x - __bfloat162float(hi));
}

__device__ __forceinline__ void mma_bf16(float* c, uint32_t a0, uint32_t a1, uint32_t a2, uint32_t a3,
                                         uint32_t b0, uint32_t b1) {
    asm volatile(
        "mma.sync.aligned.m16n8k16.row.col.f32.bf16.bf16.f32 "
        "{%0,%1,%2,%3}, {%4,%5,%6,%7}, {%8,%9}, {%0,%1,%2,%3};"
        : "+f"(c[0]), "+f"(c[1]), "+f"(c[2]), "+f"(c[3])
        : "r"(a0), "r"(a1), "r"(a2), "r"(a3), "r"(b0), "r"(b1));
}

// ---------------------------------------------------------------------------
// Prep kernel: build per-lane fragment images (hi/lo bf16 split).
// ---------------------------------------------------------------------------
__global__ __launch_bounds__(256) void prep_kernel(
    const float* __restrict__ v, const float* __restrict__ h,
    const float* __restrict__ W, const float* __restrict__ U)
{
    int gid = blockIdx.x * 256 + threadIdx.x;
    if (gid < 196608) {
        int lane = gid & 31;
        int mf   = (gid >> 5) & 3;
        int kit  = (gid >> 7) & 31;
        int tile = gid >> 12;

        int rloc = tile * 64 + mf * 16 + (lane >> 2);
        const float* r0p;
        if (tile < 32) r0p = v + (size_t)rloc * KDIM;
        else           r0p = h + (size_t)(rloc - 2048) * KDIM;
        const float* r1p = r0p + 8 * KDIM;
        int k0 = kit * 16 + (lane & 3) * 2;

        float2 x00 = *reinterpret_cast<const float2*>(r0p + k0);
        float2 x10 = *reinterpret_cast<const float2*>(r1p + k0);
        float2 x08 = *reinterpret_cast<const float2*>(r0p + k0 + 8);
        float2 x18 = *reinterpret_cast<const float2*>(r1p + k0 + 8);

        __nv_bfloat16 h00a, l00a, h00b, l00b, h10a, l10a, h10b, l10b;
        __nv_bfloat16 h08a, l08a, h08b, l08b, h18a, l18a, h18b, l18b;
        split_bf16(x00.x, h00a, l00a); split_bf16(x00.y, h00b, l00b);
        split_bf16(x10.x, h10a, l10a); split_bf16(x10.y, h10b, l10b);
        split_bf16(x08.x, h08a, l08a); split_bf16(x08.y, h08b, l08b);
        split_bf16(x18.x, h18a, l18a); split_bf16(x18.y, h18b, l18b);

        uint4 vh, vl;
        vh.x = pack2(h00a, h00b); vh.y = pack2(h10a, h10b);
        vh.z = pack2(h08a, h08b); vh.w = pack2(h18a, h18b);
        vl.x = pack2(l00a, l00b); vl.y = pack2(l10a, l10b);
        vl.z = pack2(l08a, l08b); vl.w = pack2(l18a, l18b);

        size_t base = ((((size_t)tile * KITERS + kit) * 4 + mf) * 2) * 32 + lane;
        g_Afrag[base]      = vh;
        g_Afrag[base + 32] = vl;
    } else if (gid < 262144) {
        int item = gid - 196608;
        int lane = item & 31;
        int nf   = (item >> 5) & 31;
        int kit  = (item >> 10) & 31;
        int mat  = item >> 15;                 // 0 = W, 1 = U

        const float* Bsrc = mat ? U : W;
        int n = nf * 8 + (lane >> 2);
        int k0 = kit * 16 + (lane & 3) * 2;

        float xa = Bsrc[(size_t)(k0 + 0) * PD + n];
        float xb = Bsrc[(size_t)(k0 + 1) * PD + n];
        float xc = Bsrc[(size_t)(k0 + 8) * PD + n];
        float xd = Bsrc[(size_t)(k0 + 9) * PD + n];

        __nv_bfloat16 ha, la, hb, lb, hc, lc, hd, ld;
        split_bf16(xa, ha, la); split_bf16(xb, hb, lb);
        split_bf16(xc, hc, lc); split_bf16(xd, hd, ld);

        uint4 out;
        out.x = pack2(ha, hb);
        out.y = pack2(hc, hd);
        out.z = pack2(la, lb);
        out.w = pack2(lc, ld);
        g_Bfrag[(((size_t)mat * KITERS + kit) * 32 + nf) * 32 + lane] = out;
    }
}

// ---------------------------------------------------------------------------
// bf16 split-float MMA GEMM. 192 CTAs x 256 threads (8 warps).
// CTA: 64 rows x 64 cols. Warp: 32x16 (wm in 0..1 M-half, wn in 0..3 N-quarter;
// mfrags 2 x nfrags 2). D = Ahi*Bhi + Ahi*Blo + Alo*Bhi. 12 HMMA per warp-kit.
// ---------------------------------------------------------------------------
__global__ __launch_bounds__(256) void mma_gemm_kernel(const float* __restrict__ bias)
{
    const int tile  = blockIdx.x >> 2;     // 0..47
    const int ntile = blockIdx.x & 3;      // 0..3
    const int tid   = threadIdx.x;
    const int lane  = tid & 31;
    const int wid   = tid >> 5;
    const int wm    = wid >> 2;            // 0..1 (M half, 32 rows)
    const int wn    = wid & 3;             // 0..3 (N quarter, 16 cols)
    const bool is_v = tile < 32;

    __shared__ float st[64][72];           // transpose bounce (v-tiles), padded

    float acc[2][2][4];
#pragma unroll
    for (int mf = 0; mf < 2; mf++)
#pragma unroll
        for (int nf = 0; nf < 2; nf++)
#pragma unroll
            for (int r = 0; r < 4; r++) acc[mf][nf][r] = 0.0f;

    // A base: [tile][kit][mfrag = wm*2 + mf][hl][lane]
    const uint4* Ab = g_Afrag + (((size_t)tile * KITERS * 4 + wm * 2) * 2) * 32 + lane;
    // B base: [mat][kit][nfrag = ntile*8 + wn*2 + nf][lane]
    const uint4* Bb = g_Bfrag + ((size_t)(is_v ? 0 : 1) * KITERS * 32 + (ntile * 8 + wn * 2)) * 32 + lane;

#pragma unroll 4
    for (int kit = 0; kit < KITERS; kit++) {
        const uint4* Ak = Ab + (size_t)kit * 256;     // 4*2*32 uint4 per kit
        const uint4* Bk = Bb + (size_t)kit * 1024;    // 32*32 uint4 per kit
        uint4 Ah[2], Al[2], Bf[2];
        Ah[0] = Ak[0];
        Al[0] = Ak[32];
        Ah[1] = Ak[64];
        Al[1] = Ak[96];
        Bf[0] = Bk[0];
        Bf[1] = Bk[32];
#pragma unroll
        for (int mf = 0; mf < 2; mf++) {
#pragma unroll
            for (int nf = 0; nf < 2; nf++) {
                mma_bf16(acc[mf][nf], Ah[mf].x, Ah[mf].y, Ah[mf].z, Ah[mf].w, Bf[nf].x, Bf[nf].y);
                mma_bf16(acc[mf][nf], Ah[mf].x, Ah[mf].y, Ah[mf].z, Ah[mf].w, Bf[nf].z, Bf[nf].w);
                mma_bf16(acc[mf][nf], Al[mf].x, Al[mf].y, Al[mf].z, Al[mf].w, Bf[nf].x, Bf[nf].y);
            }
        }
    }

    // Epilogue. C frag rows g/g+8, cols tc/tc+1.
    const int g  = lane >> 2;
    const int tc = (lane & 3) * 2;

    if (is_v) {
#pragma unroll
        for (int mf = 0; mf < 2; mf++) {
#pragma unroll
            for (int nf = 0; nf < 2; nf++) {
                int ml = wm * 32 + mf * 16 + g;
                int nl = wn * 16 + nf * 8 + tc;
                st[nl][ml]         = acc[mf][nf][0];
                st[nl + 1][ml]     = acc[mf][nf][1];
                st[nl][ml + 8]     = acc[mf][nf][2];
                st[nl + 1][ml + 8] = acc[mf][nf][3];
            }
        }
        __syncthreads();
        const int b  = tile >> 1;
        const int t0 = (tile & 1) * 64;
        const int d0 = ntile * 64;
        for (int i = tid; i < 64 * 16; i += 256) {
            int d  = i >> 4;
            int m4 = (i & 15) << 2;
            float4 val = *reinterpret_cast<const float4*>(&st[d][m4]);
            *reinterpret_cast<float4*>(
                g_WvT + ((size_t)(b * PD + d0 + d) << 7) + t0 + m4) = val;
        }
    } else {
#pragma unroll
        for (int mf = 0; mf < 2; mf++) {
            int row = (tile - 32) * 64 + wm * 32 + mf * 16 + g;
#pragma unroll
            for (int nf = 0; nf < 2; nf++) {
                int col = ntile * 64 + wn * 16 + nf * 8 + tc;
                float b0 = __ldg(bias + col);
                float b1 = __ldg(bias + col + 1);
                float2 o0 = make_float2(acc[mf][nf][0] + b0, acc[mf][nf][1] + b1);
                float2 o1 = make_float2(acc[mf][nf][2] + b0, acc[mf][nf][3] + b1);
                *reinterpret_cast<float2*>(g_Uhb + (size_t)row * PD + col)       = o0;
                *reinterpret_cast<float2*>(g_Uhb + (size_t)(row + 8) * PD + col) = o1;
            }
        }
    }
}

// ---------------------------------------------------------------------------
// Fused scores + softmax + context. Grid (TH/4=16, B=16) = 256 CTAs, 512 thr.
// Phase A: thread (si = tid>>7, t = tid&127): q = sum_d w[d]*tanh(Uhb+WvT)
//          -> softmax over t -> sbeta[4][128] in smem.
// Phase B: thread (si, f4 = tid&127): u[b][s0+si][4*f4..] =
//          sum_t sbeta[si][t] * v[b][t][4*f4..], unroll 8.
// ---------------------------------------------------------------------------
__global__ __launch_bounds__(512) void attn_fused_kernel(
    const float* __restrict__ v, const float* __restrict__ wvec,
    float* __restrict__ u)
{
    const int b = blockIdx.y;
    const int s0 = blockIdx.x * 4;
    const int tid = threadIdx.x;
    const int t = tid & 127;
    const int si = tid >> 7;

    __shared__ float su[4][PD];
    __shared__ float sw[PD];
    __shared__ float rmax[4][4];
    __shared__ float rsum[4][4];
    __shared__ float sbeta[4][PTV];

    if (tid < PD) sw[tid] = wvec[tid];
    for (int i = tid; i < 4 * PD; i += 512)
        su[i >> 8][i & 255] = g_Uhb[((size_t)(b * PTH + s0 + (i >> 8)) << 8) + (i & 255)];
    __syncthreads();

    // ---- Phase A: scores ----
    const float* wvt = g_WvT + ((size_t)b << 15) + t;   // stride 128 per d
    float acc = 0.0f;
#pragma unroll 8
    for (int d = 0; d < PD; d++) {
        float x = su[si][d] + wvt[(size_t)d << 7];
        acc += sw[d] * tanh_approx(x);
    }

    const int lane = t & 31;
    const int wq = t >> 5;

    float m = acc;
#pragma unroll
    for (int off = 16; off; off >>= 1)
        m = fmaxf(m, __shfl_xor_sync(0xffffffffu, m, off));
    if (lane == 0) rmax[si][wq] = m;
    __syncthreads();
    m = fmaxf(fmaxf(rmax[si][0], rmax[si][1]), fmaxf(rmax[si][2], rmax[si][3]));

    float e = __expf(acc - m);
    float ssum = e;
#pragma unroll
    for (int off = 16; off; off >>= 1)
        ssum += __shfl_xor_sync(0xffffffffu, ssum, off);
    if (lane == 0) rsum[si][wq] = ssum;
    __syncthreads();
    float total = (rsum[si][0] + rsum[si][1]) + (rsum[si][2] + rsum[si][3]);

    sbeta[si][t] = e * (1.0f / total);
    __syncthreads();

    // ---- Phase B: context ----
    const int f4 = t;               // float4 column index 0..127 (512 floats)
    float4 o = make_float4(0.f, 0.f, 0.f, 0.f);
    const float* vb = v + ((size_t)b * PTV) * PF + (f4 << 2);

#pragma unroll 8
    for (int tt = 0; tt < PTV; tt++) {
        float4 vr = *reinterpret_cast<const float4*>(vb + (size_t)tt * PF);
        float bb = sbeta[si][tt];
        o.x += bb * vr.x; o.y += bb * vr.y; o.z += bb * vr.z; o.w += bb * vr.w;
    }

    *reinterpret_cast<float4*>(u + (size_t)(b * PTH + s0 + si) * PF + (f4 << 2)) = o;
}

// ---------------------------------------------------------------------------
// kernel_launch
// Inputs: v [16,128,512], h [16,64,512], W [512,256], U [512,256], b [256], w [256,1]
// Output: u [16,64,512] float32
// ---------------------------------------------------------------------------
extern "C" void kernel_launch(void* const* d_in, const int* in_sizes, int n_in,
                              void* d_out, int out_size)
{
    const float* v    = (const float*)d_in[0];
    const float* h    = (const float*)d_in[1];
    const float* W    = (const float*)d_in[2];
    const float* U    = (const float*)d_in[3];
    const float* bvec = (const float*)d_in[4];
    const float* wvec = (const float*)d_in[5];
    float* out = (float*)d_out;

    prep_kernel<<<1024, 256>>>(v, h, W, U);
    mma_gemm_kernel<<<192, 256>>>(bvec);
    attn_fused_kernel<<<dim3(PTH / 4, PB), 512>>>(v, wvec, out);
}

// round 9
// speedup vs baseline: 1.0861x; 1.0861x over previous
#include <cuda_runtime.h>
#include <cuda_bf16.h>
#include <cstdint>

// Problem constants
#define PB  16
#define PTV 128
#define PTH 64
#define PF  512
#define PH  512
#define PD  256
#define KDIM 512

#define MTILES 48
#define KITERS 32

// ---------------------------------------------------------------------------
// Device scratch
// ---------------------------------------------------------------------------
// A fragments: [tile 48][kit 32][mfrag 4][hl 2][lane 32] : uint4
__device__ uint4 g_Afrag[MTILES * KITERS * 4 * 2 * 32];
// B fragments: [mat 2][kit 32][nfrag 32][lane 32] : uint4 {bhi01,bhi23,blo01,blo23}
__device__ uint4 g_Bfrag[2 * KITERS * 32 * 32];

__device__ float g_WvT[PB * PD * PTV];   // [b][d][t]
__device__ float g_Uhb[PB * PTH * PD];   // [b][s][d]

__device__ __forceinline__ float tanh_approx(float x) {
    float r; asm("tanh.approx.f32 %0, %1;" : "=f"(r) : "f"(x)); return r;
}
__device__ __forceinline__ uint32_t pack2(__nv_bfloat16 a, __nv_bfloat16 b) {
    return (uint32_t)__bfloat16_as_ushort(a) | ((uint32_t)__bfloat16_as_ushort(b) << 16);
}
__device__ __forceinline__ void split_bf16(float x, __nv_bfloat16& hi, __nv_bfloat16& lo) {
    hi = __float2bfloat16(x);
    lo = __float2bfloat16(x - __bfloat162float(hi));
}
__device__ __forceinline__ void mma_bf16(float* c, uint32_t a0, uint32_t a1, uint32_t a2, uint32_t a3,
                                         uint32_t b0, uint32_t b1) {
    asm volatile(
        "mma.sync.aligned.m16n8k16.row.col.f32.bf16.bf16.f32 "
        "{%0,%1,%2,%3}, {%4,%5,%6,%7}, {%8,%9}, {%0,%1,%2,%3};"
        : "+f"(c[0]), "+f"(c[1]), "+f"(c[2]), "+f"(c[3])
        : "r"(a0), "r"(a1), "r"(a2), "r"(a3), "r"(b0), "r"(b1));
}

// ---------------------------------------------------------------------------
// Prep kernel: per-lane fragment images (hi/lo bf16 split). Unchanged.
// ---------------------------------------------------------------------------
__global__ __launch_bounds__(256) void prep_kernel(
    const float* __restrict__ v, const float* __restrict__ h,
    const float* __restrict__ W, const float* __restrict__ U)
{
    int gid = blockIdx.x * 256 + threadIdx.x;
    if (gid < 196608) {
        int lane = gid & 31;
        int mf   = (gid >> 5) & 3;
        int kit  = (gid >> 7) & 31;
        int tile = gid >> 12;

        int rloc = tile * 64 + mf * 16 + (lane >> 2);
        const float* r0p;
        if (tile < 32) r0p = v + (size_t)rloc * KDIM;
        else           r0p = h + (size_t)(rloc - 2048) * KDIM;
        const float* r1p = r0p + 8 * KDIM;
        int k0 = kit * 16 + (lane & 3) * 2;

        float2 x00 = *reinterpret_cast<const float2*>(r0p + k0);
        float2 x10 = *reinterpret_cast<const float2*>(r1p + k0);
        float2 x08 = *reinterpret_cast<const float2*>(r0p + k0 + 8);
        float2 x18 = *reinterpret_cast<const float2*>(r1p + k0 + 8);

        __nv_bfloat16 h00a, l00a, h00b, l00b, h10a, l10a, h10b, l10b;
        __nv_bfloat16 h08a, l08a, h08b, l08b, h18a, l18a, h18b, l18b;
        split_bf16(x00.x, h00a, l00a); split_bf16(x00.y, h00b, l00b);
        split_bf16(x10.x, h10a, l10a); split_bf16(x10.y, h10b, l10b);
        split_bf16(x08.x, h08a, l08a); split_bf16(x08.y, h08b, l08b);
        split_bf16(x18.x, h18a, l18a); split_bf16(x18.y, h18b, l18b);

        uint4 vh, vl;
        vh.x = pack2(h00a, h00b); vh.y = pack2(h10a, h10b);
        vh.z = pack2(h08a, h08b); vh.w = pack2(h18a, h18b);
        vl.x = pack2(l00a, l00b); vl.y = pack2(l10a, l10b);
        vl.z = pack2(l08a, l08b); vl.w = pack2(l18a, l18b);

        size_t base = ((((size_t)tile * KITERS + kit) * 4 + mf) * 2) * 32 + lane;
        g_Afrag[base]      = vh;
        g_Afrag[base + 32] = vl;
    } else if (gid < 262144) {
        int item = gid - 196608;
        int lane = item & 31;
        int nf   = (item >> 5) & 31;
        int kit  = (item >> 10) & 31;
        int mat  = item >> 15;

        const float* Bsrc = mat ? U : W;
        int n = nf * 8 + (lane >> 2);
        int k0 = kit * 16 + (lane & 3) * 2;

        float xa = Bsrc[(size_t)(k0 + 0) * PD + n];
        float xb = Bsrc[(size_t)(k0 + 1) * PD + n];
        float xc = Bsrc[(size_t)(k0 + 8) * PD + n];
        float xd = Bsrc[(size_t)(k0 + 9) * PD + n];

        __nv_bfloat16 ha, la, hb, lb, hc, lc, hd, ld;
        split_bf16(xa, ha, la); split_bf16(xb, hb, lb);
        split_bf16(xc, hc, lc); split_bf16(xd, hd, ld);

        uint4 out;
        out.x = pack2(ha, hb);
        out.y = pack2(hc, hd);
        out.z = pack2(la, lb);
        out.w = pack2(lc, ld);
        g_Bfrag[(((size_t)mat * KITERS + kit) * 32 + nf) * 32 + lane] = out;
    }
}

// ---------------------------------------------------------------------------
// bf16 split-float MMA GEMM. 192 CTAs x 256 threads (8 warps).
// Per-kit fragments staged in double-buffered smem (cooperative loads, no
// cross-warp L2 duplication). Warp = 32x16 (wm 0..1, wn 0..3), 12 HMMA/kit.
// Epilogue smem overlaid on staging buffer.
// ---------------------------------------------------------------------------
__global__ __launch_bounds__(256) void mma_gemm_kernel(const float* __restrict__ bias)
{
    // staging: 2 buffers x (A 256 uint4 + B 256 uint4) = 16KB; epilogue 18KB
    __shared__ __align__(16) char s_raw[64 * 72 * 4];
    uint4* sbuf = reinterpret_cast<uint4*>(s_raw);

    const int tile  = blockIdx.x >> 2;
    const int ntile = blockIdx.x & 3;
    const int tid   = threadIdx.x;
    const int lane  = tid & 31;
    const int wid   = tid >> 5;
    const int wm    = wid >> 2;            // 0..1
    const int wn    = wid & 3;             // 0..3
    const bool is_v = tile < 32;

    float acc[2][2][4];
#pragma unroll
    for (int mf = 0; mf < 2; mf++)
#pragma unroll
        for (int nf = 0; nf < 2; nf++)
#pragma unroll
            for (int r = 0; r < 4; r++) acc[mf][nf][r] = 0.0f;

    const uint4* Asrc = g_Afrag + (size_t)tile * (KITERS * 256);           // 256 uint4 per kit
    const uint4* Bsrc = g_Bfrag + ((size_t)(is_v ? 0 : 1) * KITERS * 32 + ntile * 8) * 32;

    // prologue: load kit 0 into buffer 0
    uint4 ra = Asrc[tid];
    uint4 rb = Bsrc[tid];
    sbuf[tid] = ra;
    sbuf[256 + tid] = rb;
    __syncthreads();

    const int aoff0 = ((wm * 2 + 0) * 2) * 32 + lane;   // Ah mf=0
    const int boff0 = 256 + (wn * 2) * 32 + lane;       // Bf nf=0

    for (int kit = 0; kit < KITERS; kit++) {
        const int p = kit & 1;
        if (kit < KITERS - 1) {
            ra = Asrc[(size_t)(kit + 1) * 256 + tid];
            rb = Bsrc[(size_t)(kit + 1) * 1024 + tid];
        }
        const uint4* buf = sbuf + p * 512;
        uint4 Ah[2], Al[2], Bf[2];
        Ah[0] = buf[aoff0];
        Al[0] = buf[aoff0 + 32];
        Ah[1] = buf[aoff0 + 64];
        Al[1] = buf[aoff0 + 96];
        Bf[0] = buf[boff0];
        Bf[1] = buf[boff0 + 32];
#pragma unroll
        for (int mf = 0; mf < 2; mf++) {
#pragma unroll
            for (int nf = 0; nf < 2; nf++) {
                mma_bf16(acc[mf][nf], Ah[mf].x, Ah[mf].y, Ah[mf].z, Ah[mf].w, Bf[nf].x, Bf[nf].y);
                mma_bf16(acc[mf][nf], Ah[mf].x, Ah[mf].y, Ah[mf].z, Ah[mf].w, Bf[nf].z, Bf[nf].w);
                mma_bf16(acc[mf][nf], Al[mf].x, Al[mf].y, Al[mf].z, Al[mf].w, Bf[nf].x, Bf[nf].y);
            }
        }
        __syncthreads();                    // done reading buffer p
        if (kit < KITERS - 1) {
            uint4* dst = sbuf + (p ^ 1) * 512;
            dst[tid] = ra;
            dst[256 + tid] = rb;
            __syncthreads();                // STS visible before next iter reads
        }
    }

    // Epilogue. C frag rows g/g+8, cols tc/tc+1.
    const int g  = lane >> 2;
    const int tc = (lane & 3) * 2;

    if (is_v) {
        float (*st)[72] = reinterpret_cast<float (*)[72]>(s_raw);
#pragma unroll
        for (int mf = 0; mf < 2; mf++) {
#pragma unroll
            for (int nf = 0; nf < 2; nf++) {
                int ml = wm * 32 + mf * 16 + g;
                int nl = wn * 16 + nf * 8 + tc;
                st[nl][ml]         = acc[mf][nf][0];
                st[nl + 1][ml]     = acc[mf][nf][1];
                st[nl][ml + 8]     = acc[mf][nf][2];
                st[nl + 1][ml + 8] = acc[mf][nf][3];
            }
        }
        __syncthreads();
        const int b  = tile >> 1;
        const int t0 = (tile & 1) * 64;
        const int d0 = ntile * 64;
        for (int i = tid; i < 64 * 16; i += 256) {
            int d  = i >> 4;
            int m4 = (i & 15) << 2;
            float4 val = *reinterpret_cast<const float4*>(&st[d][m4]);
            *reinterpret_cast<float4*>(
                g_WvT + ((size_t)(b * PD + d0 + d) << 7) + t0 + m4) = val;
        }
    } else {
#pragma unroll
        for (int mf = 0; mf < 2; mf++) {
            int row = (tile - 32) * 64 + wm * 32 + mf * 16 + g;
#pragma unroll
            for (int nf = 0; nf < 2; nf++) {
                int col = ntile * 64 + wn * 16 + nf * 8 + tc;
                float b0 = __ldg(bias + col);
                float b1 = __ldg(bias + col + 1);
                float2 o0 = make_float2(acc[mf][nf][0] + b0, acc[mf][nf][1] + b1);
                float2 o1 = make_float2(acc[mf][nf][2] + b0, acc[mf][nf][3] + b1);
                *reinterpret_cast<float2*>(g_Uhb + (size_t)row * PD + col)       = o0;
                *reinterpret_cast<float2*>(g_Uhb + (size_t)(row + 8) * PD + col) = o1;
            }
        }
    }
}

// ---------------------------------------------------------------------------
// Fused scores + softmax + context. Grid (TH/4=16, B=16) = 256 CTAs, 512 thr.
// Phase A: WvT[b] streamed through smem in 8 chunks of 32 d (double-buffered)
//          so the 128KB slice is read from L2 ONCE per CTA (was 4x).
//          q = sum_d w[d]*tanh(Uhb[s,d] + WvT[b,d,t]); softmax -> sbeta.
// Phase B: u[b][s0+si][4*f4..] = sum_t sbeta[si][t]*v[b][t][4*f4..].
// ---------------------------------------------------------------------------
__global__ __launch_bounds__(512) void attn_fused_kernel(
    const float* __restrict__ v, const float* __restrict__ wvec,
    float* __restrict__ u)
{
    const int b = blockIdx.y;
    const int s0 = blockIdx.x * 4;
    const int tid = threadIdx.x;
    const int t = tid & 127;
    const int si = tid >> 7;

    __shared__ float su[4][PD];
    __shared__ float sw[PD];
    __shared__ float rmax[4][4];
    __shared__ float rsum[4][4];
    __shared__ float sbeta[4][PTV];
    __shared__ float4 sbuf[2][1024];    // 2 x (32 d x 128 t) = 2 x 16KB

    if (tid < PD) sw[tid] = wvec[tid];
    for (int i = tid; i < 4 * PD; i += 512)
        su[i >> 8][i & 255] = g_Uhb[((size_t)(b * PTH + s0 + (i >> 8)) << 8) + (i & 255)];

    const float4* wsrc = reinterpret_cast<const float4*>(g_WvT + ((size_t)b << 15));
    // prologue: chunk 0 (rows d 0..31), thread loads float4 idx tid and tid+512
    float4 r0 = wsrc[tid];
    float4 r1 = wsrc[tid + 512];
    sbuf[0][tid] = r0;
    sbuf[0][tid + 512] = r1;
    __syncthreads();

    float accA = 0.0f, accB = 0.0f;
    for (int c = 0; c < 8; c++) {
        const int p = c & 1;
        if (c < 7) {
            r0 = wsrc[(size_t)(c + 1) * 1024 + tid];
            r1 = wsrc[(size_t)(c + 1) * 1024 + tid + 512];
        }
        const float* wb = reinterpret_cast<const float*>(sbuf[p]);  // [32][128]
        const float* sud = &su[si][c * 32];
        const float* swd = &sw[c * 32];
#pragma unroll
        for (int dd = 0; dd < 32; dd += 2) {
            float x0 = sud[dd]     + wb[dd * 128 + t];
            float x1 = sud[dd + 1] + wb[(dd + 1) * 128 + t];
            accA += swd[dd]     * tanh_approx(x0);
            accB += swd[dd + 1] * tanh_approx(x1);
        }
        __syncthreads();
        if (c < 7) {
            sbuf[p ^ 1][tid] = r0;
            sbuf[p ^ 1][tid + 512] = r1;
            __syncthreads();
        }
    }
    float acc = accA + accB;

    // softmax over t (4 warps per si)
    const int lane = t & 31;
    const int wq = t >> 5;

    float m = acc;
#pragma unroll
    for (int off = 16; off; off >>= 1)
        m = fmaxf(m, __shfl_xor_sync(0xffffffffu, m, off));
    if (lane == 0) rmax[si][wq] = m;
    __syncthreads();
    m = fmaxf(fmaxf(rmax[si][0], rmax[si][1]), fmaxf(rmax[si][2], rmax[si][3]));

    float e = __expf(acc - m);
    float ssum = e;
#pragma unroll
    for (int off = 16; off; off >>= 1)
        ssum += __shfl_xor_sync(0xffffffffu, ssum, off);
    if (lane == 0) rsum[si][wq] = ssum;
    __syncthreads();
    float total = (rsum[si][0] + rsum[si][1]) + (rsum[si][2] + rsum[si][3]);

    sbeta[si][t] = e * (1.0f / total);
    __syncthreads();

    // Phase B: context
    const int f4 = t;
    float4 o = make_float4(0.f, 0.f, 0.f, 0.f);
    const float* vb = v + ((size_t)b * PTV) * PF + (f4 << 2);

#pragma unroll 8
    for (int tt = 0; tt < PTV; tt++) {
        float4 vr = *reinterpret_cast<const float4*>(vb + (size_t)tt * PF);
        float bb = sbeta[si][tt];
        o.x += bb * vr.x; o.y += bb * vr.y; o.z += bb * vr.z; o.w += bb * vr.w;
    }

    *reinterpret_cast<float4*>(u + (size_t)(b * PTH + s0 + si) * PF + (f4 << 2)) = o;
}

// ---------------------------------------------------------------------------
// kernel_launch
// Inputs: v [16,128,512], h [16,64,512], W [512,256], U [512,256], b [256], w [256,1]
// Output: u [16,64,512] float32
// ---------------------------------------------------------------------------
extern "C" void kernel_launch(void* const* d_in, const int* in_sizes, int n_in,
                              void* d_out, int out_size)
{
    const float* v    = (const float*)d_in[0];
    const float* h    = (const float*)d_in[1];
    const float* W    = (const float*)d_in[2];
    const float* U    = (const float*)d_in[3];
    const float* bvec = (const float*)d_in[4];
    const float* wvec = (const float*)d_in[5];
    float* out = (float*)d_out;

    prep_kernel<<<1024, 256>>>(v, h, W, U);
    mma_gemm_kernel<<<192, 256>>>(bvec);
    attn_fused_kernel<<<dim3(PTH / 4, PB), 512>>>(v, wvec, out);
}

// round 10
// speedup vs baseline: 1.1454x; 1.0546x over previous
#include <cuda_runtime.h>
#include <cuda_bf16.h>
#include <cstdint>

// Problem constants
#define PB  16
#define PTV 128
#define PTH 64
#define PF  512
#define PH  512
#define PD  256
#define KDIM 512

#define MTILES 48
#define KITERS 32

// ---------------------------------------------------------------------------
// Device scratch
// ---------------------------------------------------------------------------
// A fragments: [tile 48][kit 32][mfrag 4][hl 2][lane 32] : uint4
__device__ uint4 g_Afrag[MTILES * KITERS * 4 * 2 * 32];
// B fragments: [mat 2][kit 32][nfrag 32][lane 32] : uint4 {bhi01,bhi23,blo01,blo23}
__device__ uint4 g_Bfrag[2 * KITERS * 32 * 32];

__device__ float g_WvT[PB * PD * PTV];   // [b][d][t]
__device__ float g_Uhb[PB * PTH * PD];   // [b][s][d]

__device__ __forceinline__ float tanh_approx(float x) {
    float r; asm("tanh.approx.f32 %0, %1;" : "=f"(r) : "f"(x)); return r;
}
__device__ __forceinline__ uint32_t smem_u32(const void* p) {
    uint32_t a;
    asm("{ .reg .u64 t; cvta.to.shared.u64 t, %1; cvt.u32.u64 %0, t; }" : "=r"(a) : "l"(p));
    return a;
}
__device__ __forceinline__ void cp_async16(uint32_t smem_addr, const void* gptr) {
    asm volatile("cp.async.cg.shared.global [%0], [%1], 16;" :: "r"(smem_addr), "l"(gptr));
}
#define CP_COMMIT() asm volatile("cp.async.commit_group;" ::: "memory")
#define CP_WAIT(N)  asm volatile("cp.async.wait_group %0;" :: "n"(N) : "memory")

// Split-pair: returns packed {lo16: bf16hi(a), hi16: bf16hi(b)}; lop gets the
// lo-residual pair. Per-element identical to __float2bfloat16 (rn) splits.
__device__ __forceinline__ uint32_t splitpair(float a, float b, uint32_t& lop) {
    uint32_t hp;
    asm("cvt.rn.bf16x2.f32 %0, %1, %2;" : "=r"(hp) : "f"(b), "f"(a));
    float ha = __uint_as_float(hp << 16);            // bf16 -> f32 is a shift
    float hb = __uint_as_float(hp & 0xFFFF0000u);
    float la = a - ha;
    float lb = b - hb;
    asm("cvt.rn.bf16x2.f32 %0, %1, %2;" : "=r"(lop) : "f"(lb), "f"(la));
    return hp;
}

__device__ __forceinline__ void mma_bf16(float* c, uint32_t a0, uint32_t a1, uint32_t a2, uint32_t a3,
                                         uint32_t b0, uint32_t b1) {
    asm volatile(
        "mma.sync.aligned.m16n8k16.row.col.f32.bf16.bf16.f32 "
        "{%0,%1,%2,%3}, {%4,%5,%6,%7}, {%8,%9}, {%0,%1,%2,%3};"
        : "+f"(c[0]), "+f"(c[1]), "+f"(c[2]), "+f"(c[3])
        : "r"(a0), "r"(a1), "r"(a2), "r"(a3), "r"(b0), "r"(b1));
}

// ---------------------------------------------------------------------------
// Prep kernel: per-lane fragment images (hi/lo bf16 split), bf16x2 cvts.
// ---------------------------------------------------------------------------
__global__ __launch_bounds__(256) void prep_kernel(
    const float* __restrict__ v, const float* __restrict__ h,
    const float* __restrict__ W, const float* __restrict__ U)
{
    int gid = blockIdx.x * 256 + threadIdx.x;
    if (gid < 196608) {
        int lane = gid & 31;
        int mf   = (gid >> 5) & 3;
        int kit  = (gid >> 7) & 31;
        int tile = gid >> 12;

        int rloc = tile * 64 + mf * 16 + (lane >> 2);
        const float* r0p;
        if (tile < 32) r0p = v + (size_t)rloc * KDIM;
        else           r0p = h + (size_t)(rloc - 2048) * KDIM;
        const float* r1p = r0p + 8 * KDIM;
        int k0 = kit * 16 + (lane & 3) * 2;

        float2 x00 = *reinterpret_cast<const float2*>(r0p + k0);
        float2 x10 = *reinterpret_cast<const float2*>(r1p + k0);
        float2 x08 = *reinterpret_cast<const float2*>(r0p + k0 + 8);
        float2 x18 = *reinterpret_cast<const float2*>(r1p + k0 + 8);

        uint4 vh, vl;
        vh.x = splitpair(x00.x, x00.y, vl.x);
        vh.y = splitpair(x10.x, x10.y, vl.y);
        vh.z = splitpair(x08.x, x08.y, vl.z);
        vh.w = splitpair(x18.x, x18.y, vl.w);

        size_t base = ((((size_t)tile * KITERS + kit) * 4 + mf) * 2) * 32 + lane;
        g_Afrag[base]      = vh;
        g_Afrag[base + 32] = vl;
    } else if (gid < 262144) {
        int item = gid - 196608;
        int lane = item & 31;
        int nf   = (item >> 5) & 31;
        int kit  = (item >> 10) & 31;
        int mat  = item >> 15;

        const float* Bsrc = mat ? U : W;
        int n = nf * 8 + (lane >> 2);
        int k0 = kit * 16 + (lane & 3) * 2;

        float xa = Bsrc[(size_t)(k0 + 0) * PD + n];
        float xb = Bsrc[(size_t)(k0 + 1) * PD + n];
        float xc = Bsrc[(size_t)(k0 + 8) * PD + n];
        float xd = Bsrc[(size_t)(k0 + 9) * PD + n];

        uint4 out;
        out.x = splitpair(xa, xb, out.z);
        out.y = splitpair(xc, xd, out.w);
        g_Bfrag[(((size_t)mat * KITERS + kit) * 32 + nf) * 32 + lane] = out;
    }
}

// ---------------------------------------------------------------------------
// bf16 split-float MMA GEMM. 192 CTAs x 256 threads (8 warps).
// 4-stage cp.async pipeline (depth-3 prefetch), ONE barrier per kit.
// Stage: A 256 uint4 + B 256 uint4 = 8KB; 4 stages = 32KB, epilogue overlaid.
// Warp = 32x16 (wm 0..1, wn 0..3), 12 HMMA/kit.
// ---------------------------------------------------------------------------
__global__ __launch_bounds__(256) void mma_gemm_kernel(const float* __restrict__ bias)
{
    __shared__ __align__(16) char s_raw[32768];
    uint4* sbuf = reinterpret_cast<uint4*>(s_raw);
    const uint32_t sbase = smem_u32(s_raw);

    const int tile  = blockIdx.x >> 2;
    const int ntile = blockIdx.x & 3;
    const int tid   = threadIdx.x;
    const int lane  = tid & 31;
    const int wid   = tid >> 5;
    const int wm    = wid >> 2;            // 0..1
    const int wn    = wid & 3;             // 0..3
    const bool is_v = tile < 32;

    float acc[2][2][4];
#pragma unroll
    for (int mf = 0; mf < 2; mf++)
#pragma unroll
        for (int nf = 0; nf < 2; nf++)
#pragma unroll
            for (int r = 0; r < 4; r++) acc[mf][nf][r] = 0.0f;

    const uint4* Asrc = g_Afrag + (size_t)tile * (KITERS * 256);
    const uint4* Bsrc = g_Bfrag + ((size_t)(is_v ? 0 : 1) * KITERS * 32 + ntile * 8) * 32;

    // prologue: stages 0..2 <- kits 0..2 (3 groups)
#pragma unroll
    for (int s = 0; s < 3; s++) {
        cp_async16(sbase + (s * 512 + tid) * 16,       Asrc + (size_t)s * 256 + tid);
        cp_async16(sbase + (s * 512 + 256 + tid) * 16, Bsrc + (size_t)s * 1024 + tid);
        CP_COMMIT();
    }

    const int aoff0 = ((wm * 2 + 0) * 2) * 32 + lane;   // Ah mf=0 within stage
    const int boff0 = 256 + (wn * 2) * 32 + lane;       // Bf nf=0 within stage

#pragma unroll 4
    for (int kit = 0; kit < KITERS; kit++) {
        const int p = kit & 3;
        CP_WAIT(2);                 // groups 0..kit complete
        __syncthreads();            // all threads done reading stage (kit-1)&3
        if (kit + 3 < KITERS) {
            const int s = (kit + 3) & 3;
            cp_async16(sbase + (s * 512 + tid) * 16,       Asrc + (size_t)(kit + 3) * 256 + tid);
            cp_async16(sbase + (s * 512 + 256 + tid) * 16, Bsrc + (size_t)(kit + 3) * 1024 + tid);
        }
        CP_COMMIT();                // always one group per iter (may be empty)

        const uint4* buf = sbuf + p * 512;
        uint4 Ah[2], Al[2], Bf[2];
        Ah[0] = buf[aoff0];
        Al[0] = buf[aoff0 + 32];
        Ah[1] = buf[aoff0 + 64];
        Al[1] = buf[aoff0 + 96];
        Bf[0] = buf[boff0];
        Bf[1] = buf[boff0 + 32];
#pragma unroll
        for (int mf = 0; mf < 2; mf++) {
#pragma unroll
            for (int nf = 0; nf < 2; nf++) {
                mma_bf16(acc[mf][nf], Ah[mf].x, Ah[mf].y, Ah[mf].z, Ah[mf].w, Bf[nf].x, Bf[nf].y);
                mma_bf16(acc[mf][nf], Ah[mf].x, Ah[mf].y, Ah[mf].z, Ah[mf].w, Bf[nf].z, Bf[nf].w);
                mma_bf16(acc[mf][nf], Al[mf].x, Al[mf].y, Al[mf].z, Al[mf].w, Bf[nf].x, Bf[nf].y);
            }
        }
    }
    __syncthreads();    // all reads done; remaining groups are empty (no writes)

    // Epilogue. C frag rows g/g+8, cols tc/tc+1.
    const int g  = lane >> 2;
    const int tc = (lane & 3) * 2;

    if (is_v) {
        float (*st)[72] = reinterpret_cast<float (*)[72]>(s_raw);
#pragma unroll
        for (int mf = 0; mf < 2; mf++) {
#pragma unroll
            for (int nf = 0; nf < 2; nf++) {
                int ml = wm * 32 + mf * 16 + g;
                int nl = wn * 16 + nf * 8 + tc;
                st[nl][ml]         = acc[mf][nf][0];
                st[nl + 1][ml]     = acc[mf][nf][1];
                st[nl][ml + 8]     = acc[mf][nf][2];
                st[nl + 1][ml + 8] = acc[mf][nf][3];
            }
        }
        __syncthreads();
        const int b  = tile >> 1;
        const int t0 = (tile & 1) * 64;
        const int d0 = ntile * 64;
        for (int i = tid; i < 64 * 16; i += 256) {
            int d  = i >> 4;
            int m4 = (i & 15) << 2;
            float4 val = *reinterpret_cast<const float4*>(&st[d][m4]);
            *reinterpret_cast<float4*>(
                g_WvT + ((size_t)(b * PD + d0 + d) << 7) + t0 + m4) = val;
        }
    } else {
#pragma unroll
        for (int mf = 0; mf < 2; mf++) {
            int row = (tile - 32) * 64 + wm * 32 + mf * 16 + g;
#pragma unroll
            for (int nf = 0; nf < 2; nf++) {
                int col = ntile * 64 + wn * 16 + nf * 8 + tc;
                float b0 = __ldg(bias + col);
                float b1 = __ldg(bias + col + 1);
                float2 o0 = make_float2(acc[mf][nf][0] + b0, acc[mf][nf][1] + b1);
                float2 o1 = make_float2(acc[mf][nf][2] + b0, acc[mf][nf][3] + b1);
                *reinterpret_cast<float2*>(g_Uhb + (size_t)row * PD + col)       = o0;
                *reinterpret_cast<float2*>(g_Uhb + (size_t)(row + 8) * PD + col) = o1;
            }
        }
    }
}

// ---------------------------------------------------------------------------
// Fused scores + softmax + context. Grid (TH/4=16, B=16) = 256 CTAs, 512 thr.
// Phase A: WvT[b] streamed via 2-stage cp.async (8 chunks of 32 d x 128 t);
//          copy of chunk c+1 overlaps MUFU compute of chunk c; 1 barrier/chunk.
// Phase B: u[b][s0+si][4*f4..] = sum_t sbeta[si][t]*v[b][t][4*f4..].
// ---------------------------------------------------------------------------
__global__ __launch_bounds__(512) void attn_fused_kernel(
    const float* __restrict__ v, const float* __restrict__ wvec,
    float* __restrict__ u)
{
    const int b = blockIdx.y;
    const int s0 = blockIdx.x * 4;
    const int tid = threadIdx.x;
    const int t = tid & 127;
    const int si = tid >> 7;

    __shared__ float su[4][PD];
    __shared__ float sw[PD];
    __shared__ float rmax[4][4];
    __shared__ float rsum[4][4];
    __shared__ float sbeta[4][PTV];
    __shared__ __align__(16) float4 sbuf[2][1024];    // 2 x 16KB

    const uint32_t sb_addr = smem_u32(sbuf);

    if (tid < PD) sw[tid] = wvec[tid];
    for (int i = tid; i < 4 * PD; i += 512)
        su[i >> 8][i & 255] = g_Uhb[((size_t)(b * PTH + s0 + (i >> 8)) << 8) + (i & 255)];

    const float4* wsrc = reinterpret_cast<const float4*>(g_WvT + ((size_t)b << 15));
    // prologue: chunk 0 -> stage 0
    cp_async16(sb_addr + tid * 16,         wsrc + tid);
    cp_async16(sb_addr + (512 + tid) * 16, wsrc + 512 + tid);
    CP_COMMIT();

    float accA = 0.0f, accB = 0.0f;
    for (int c = 0; c < 8; c++) {
        const int p = c & 1;
        CP_WAIT(0);                 // chunk c resident
        __syncthreads();            // (also publishes su/sw on c==0)
        if (c + 1 < 8) {
            const float4* src = wsrc + (size_t)(c + 1) * 1024;
            uint32_t dst = sb_addr + ((p ^ 1) * 1024 + tid) * 16;
            cp_async16(dst,            src + tid);
            cp_async16(dst + 512 * 16, src + 512 + tid);
        }
        CP_COMMIT();

        const float* wb = reinterpret_cast<const float*>(sbuf[p]);  // [32][128]
        const float* sud = &su[si][c * 32];
        const float* swd = &sw[c * 32];
#pragma unroll
        for (int dd = 0; dd < 32; dd += 2) {
            float x0 = sud[dd]     + wb[dd * 128 + t];
            float x1 = sud[dd + 1] + wb[(dd + 1) * 128 + t];
            accA += swd[dd]     * tanh_approx(x0);
            accB += swd[dd + 1] * tanh_approx(x1);
        }
    }
    float acc = accA + accB;

    // softmax over t (4 warps per si)
    const int lane = t & 31;
    const int wq = t >> 5;

    float m = acc;
#pragma unroll
    for (int off = 16; off; off >>= 1)
        m = fmaxf(m, __shfl_xor_sync(0xffffffffu, m, off));
    if (lane == 0) rmax[si][wq] = m;
    __syncthreads();
    m = fmaxf(fmaxf(rmax[si][0], rmax[si][1]), fmaxf(rmax[si][2], rmax[si][3]));

    float e = __expf(acc - m);
    float ssum = e;
#pragma unroll
    for (int off = 16; off; off >>= 1)
        ssum += __shfl_xor_sync(0xffffffffu, ssum, off);
    if (lane == 0) rsum[si][wq] = ssum;
    __syncthreads();
    float total = (rsum[si][0] + rsum[si][1]) + (rsum[si][2] + rsum[si][3]);

    sbeta[si][t] = e * (1.0f / total);
    __syncthreads();

    // Phase B: context
    const int f4 = t;
    float4 o = make_float4(0.f, 0.f, 0.f, 0.f);
    const float* vb = v + ((size_t)b * PTV) * PF + (f4 << 2);

#pragma unroll 8
    for (int tt = 0; tt < PTV; tt++) {
        float4 vr = *reinterpret_cast<const float4*>(vb + (size_t)tt * PF);
        float bb = sbeta[si][tt];
        o.x += bb * vr.x; o.y += bb * vr.y; o.z += bb * vr.z; o.w += bb * vr.w;
    }

    *reinterpret_cast<float4*>(u + (size_t)(b * PTH + s0 + si) * PF + (f4 << 2)) = o;
}

// ---------------------------------------------------------------------------
// kernel_launch
// Inputs: v [16,128,512], h [16,64,512], W [512,256], U [512,256], b [256], w [256,1]
// Output: u [16,64,512] float32
// ---------------------------------------------------------------------------
extern "C" void kernel_launch(void* const* d_in, const int* in_sizes, int n_in,
                              void* d_out, int out_size)
{
    const float* v    = (const float*)d_in[0];
    const float* h    = (const float*)d_in[1];
    const float* W    = (const float*)d_in[2];
    const float* U    = (const float*)d_in[3];
    const float* bvec = (const float*)d_in[4];
    const float* wvec = (const float*)d_in[5];
    float* out = (float*)d_out;

    prep_kernel<<<1024, 256>>>(v, h, W, U);
    mma_gemm_kernel<<<192, 256>>>(bvec);
    attn_fused_kernel<<<dim3(PTH / 4, PB), 512>>>(v, wvec, out);
}

// round 11
// speedup vs baseline: 1.3827x; 1.2072x over previous
#include <cuda_runtime.h>
#include <cuda_bf16.h>
#include <cstdint>

// Problem constants
#define PB  16
#define PTV 128
#define PTH 64
#define PF  512
#define PH  512
#define PD  256
#define KDIM 512

#define MTILES 48
#define KITERS 32

// ---------------------------------------------------------------------------
// Device scratch
// ---------------------------------------------------------------------------
__device__ uint4 g_Afrag[MTILES * KITERS * 4 * 2 * 32];
__device__ uint4 g_Bfrag[2 * KITERS * 32 * 32];

__device__ float g_WvT[PB * PD * PTV];   // [b][d][t]
__device__ float g_Uhb[PB * PTH * PD];   // [b][s][d]

__device__ __forceinline__ float tanh_approx(float x) {
    float r; asm("tanh.approx.f32 %0, %1;" : "=f"(r) : "f"(x)); return r;
}
__device__ __forceinline__ uint32_t smem_u32(const void* p) {
    uint32_t a;
    asm("{ .reg .u64 t; cvta.to.shared.u64 t, %1; cvt.u32.u64 %0, t; }" : "=r"(a) : "l"(p));
    return a;
}
__device__ __forceinline__ void cp_async16(uint32_t smem_addr, const void* gptr) {
    asm volatile("cp.async.cg.shared.global [%0], [%1], 16;" :: "r"(smem_addr), "l"(gptr));
}
#define CP_COMMIT() asm volatile("cp.async.commit_group;" ::: "memory")
#define CP_WAIT(N)  asm volatile("cp.async.wait_group %0;" :: "n"(N) : "memory")

// Split-pair: packed bf16-hi of (a,b); lop gets residual pair.
__device__ __forceinline__ uint32_t splitpair(float a, float b, uint32_t& lop) {
    uint32_t hp;
    asm("cvt.rn.bf16x2.f32 %0, %1, %2;" : "=r"(hp) : "f"(b), "f"(a));
    float ha = __uint_as_float(hp << 16);
    float hb = __uint_as_float(hp & 0xFFFF0000u);
    float la = a - ha;
    float lb = b - hb;
    asm("cvt.rn.bf16x2.f32 %0, %1, %2;" : "=r"(lop) : "f"(lb), "f"(la));
    return hp;
}

__device__ __forceinline__ void mma_bf16(float* c, uint32_t a0, uint32_t a1, uint32_t a2, uint32_t a3,
                                         uint32_t b0, uint32_t b1) {
    asm volatile(
        "mma.sync.aligned.m16n8k16.row.col.f32.bf16.bf16.f32 "
        "{%0,%1,%2,%3}, {%4,%5,%6,%7}, {%8,%9}, {%0,%1,%2,%3};"
        : "+f"(c[0]), "+f"(c[1]), "+f"(c[2]), "+f"(c[3])
        : "r"(a0), "r"(a1), "r"(a2), "r"(a3), "r"(b0), "r"(b1));
}

// ---------------------------------------------------------------------------
// Prep kernel (unchanged from round 10)
// ---------------------------------------------------------------------------
__global__ __launch_bounds__(256) void prep_kernel(
    const float* __restrict__ v, const float* __restrict__ h,
    const float* __restrict__ W, const float* __restrict__ U)
{
    int gid = blockIdx.x * 256 + threadIdx.x;
    if (gid < 196608) {
        int lane = gid & 31;
        int mf   = (gid >> 5) & 3;
        int kit  = (gid >> 7) & 31;
        int tile = gid >> 12;

        int rloc = tile * 64 + mf * 16 + (lane >> 2);
        const float* r0p;
        if (tile < 32) r0p = v + (size_t)rloc * KDIM;
        else           r0p = h + (size_t)(rloc - 2048) * KDIM;
        const float* r1p = r0p + 8 * KDIM;
        int k0 = kit * 16 + (lane & 3) * 2;

        float2 x00 = *reinterpret_cast<const float2*>(r0p + k0);
        float2 x10 = *reinterpret_cast<const float2*>(r1p + k0);
        float2 x08 = *reinterpret_cast<const float2*>(r0p + k0 + 8);
        float2 x18 = *reinterpret_cast<const float2*>(r1p + k0 + 8);

        uint4 vh, vl;
        vh.x = splitpair(x00.x, x00.y, vl.x);
        vh.y = splitpair(x10.x, x10.y, vl.y);
        vh.z = splitpair(x08.x, x08.y, vl.z);
        vh.w = splitpair(x18.x, x18.y, vl.w);

        size_t base = ((((size_t)tile * KITERS + kit) * 4 + mf) * 2) * 32 + lane;
        g_Afrag[base]      = vh;
        g_Afrag[base + 32] = vl;
    } else if (gid < 262144) {
        int item = gid - 196608;
        int lane = item & 31;
        int nf   = (item >> 5) & 31;
        int kit  = (item >> 10) & 31;
        int mat  = item >> 15;

        const float* Bsrc = mat ? U : W;
        int n = nf * 8 + (lane >> 2);
        int k0 = kit * 16 + (lane & 3) * 2;

        float xa = Bsrc[(size_t)(k0 + 0) * PD + n];
        float xb = Bsrc[(size_t)(k0 + 1) * PD + n];
        float xc = Bsrc[(size_t)(k0 + 8) * PD + n];
        float xd = Bsrc[(size_t)(k0 + 9) * PD + n];

        uint4 out;
        out.x = splitpair(xa, xb, out.z);
        out.y = splitpair(xc, xd, out.w);
        g_Bfrag[(((size_t)mat * KITERS + kit) * 32 + nf) * 32 + lane] = out;
    }
}

// ---------------------------------------------------------------------------
// bf16 split-float MMA GEMM (unchanged from round 10)
// ---------------------------------------------------------------------------
__global__ __launch_bounds__(256) void mma_gemm_kernel(const float* __restrict__ bias)
{
    __shared__ __align__(16) char s_raw[32768];
    uint4* sbuf = reinterpret_cast<uint4*>(s_raw);
    const uint32_t sbase = smem_u32(s_raw);

    const int tile  = blockIdx.x >> 2;
    const int ntile = blockIdx.x & 3;
    const int tid   = threadIdx.x;
    const int lane  = tid & 31;
    const int wid   = tid >> 5;
    const int wm    = wid >> 2;
    const int wn    = wid & 3;
    const bool is_v = tile < 32;

    float acc[2][2][4];
#pragma unroll
    for (int mf = 0; mf < 2; mf++)
#pragma unroll
        for (int nf = 0; nf < 2; nf++)
#pragma unroll
            for (int r = 0; r < 4; r++) acc[mf][nf][r] = 0.0f;

    const uint4* Asrc = g_Afrag + (size_t)tile * (KITERS * 256);
    const uint4* Bsrc = g_Bfrag + ((size_t)(is_v ? 0 : 1) * KITERS * 32 + ntile * 8) * 32;

#pragma unroll
    for (int s = 0; s < 3; s++) {
        cp_async16(sbase + (s * 512 + tid) * 16,       Asrc + (size_t)s * 256 + tid);
        cp_async16(sbase + (s * 512 + 256 + tid) * 16, Bsrc + (size_t)s * 1024 + tid);
        CP_COMMIT();
    }

    const int aoff0 = ((wm * 2 + 0) * 2) * 32 + lane;
    const int boff0 = 256 + (wn * 2) * 32 + lane;

#pragma unroll 4
    for (int kit = 0; kit < KITERS; kit++) {
        const int p = kit & 3;
        CP_WAIT(2);
        __syncthreads();
        if (kit + 3 < KITERS) {
            const int s = (kit + 3) & 3;
            cp_async16(sbase + (s * 512 + tid) * 16,       Asrc + (size_t)(kit + 3) * 256 + tid);
            cp_async16(sbase + (s * 512 + 256 + tid) * 16, Bsrc + (size_t)(kit + 3) * 1024 + tid);
        }
        CP_COMMIT();

        const uint4* buf = sbuf + p * 512;
        uint4 Ah[2], Al[2], Bf[2];
        Ah[0] = buf[aoff0];
        Al[0] = buf[aoff0 + 32];
        Ah[1] = buf[aoff0 + 64];
        Al[1] = buf[aoff0 + 96];
        Bf[0] = buf[boff0];
        Bf[1] = buf[boff0 + 32];
#pragma unroll
        for (int mf = 0; mf < 2; mf++) {
#pragma unroll
            for (int nf = 0; nf < 2; nf++) {
                mma_bf16(acc[mf][nf], Ah[mf].x, Ah[mf].y, Ah[mf].z, Ah[mf].w, Bf[nf].x, Bf[nf].y);
                mma_bf16(acc[mf][nf], Ah[mf].x, Ah[mf].y, Ah[mf].z, Ah[mf].w, Bf[nf].z, Bf[nf].w);
                mma_bf16(acc[mf][nf], Al[mf].x, Al[mf].y, Al[mf].z, Al[mf].w, Bf[nf].x, Bf[nf].y);
            }
        }
    }
    __syncthreads();

    const int g  = lane >> 2;
    const int tc = (lane & 3) * 2;

    if (is_v) {
        float (*st)[72] = reinterpret_cast<float (*)[72]>(s_raw);
        // NOTE: 64x72 floats = 18KB > 32KB buffer? 64*72*4 = 18432 < 32768 OK
#pragma unroll
        for (int mf = 0; mf < 2; mf++) {
#pragma unroll
            for (int nf = 0; nf < 2; nf++) {
                int ml = wm * 32 + mf * 16 + g;
                int nl = wn * 16 + nf * 8 + tc;
                st[nl][ml]         = acc[mf][nf][0];
                st[nl + 1][ml]     = acc[mf][nf][1];
                st[nl][ml + 8]     = acc[mf][nf][2];
                st[nl + 1][ml + 8] = acc[mf][nf][3];
            }
        }
        __syncthreads();
        const int b  = tile >> 1;
        const int t0 = (tile & 1) * 64;
        const int d0 = ntile * 64;
        for (int i = tid; i < 64 * 16; i += 256) {
            int d  = i >> 4;
            int m4 = (i & 15) << 2;
            float4 val = *reinterpret_cast<const float4*>(&st[d][m4]);
            *reinterpret_cast<float4*>(
                g_WvT + ((size_t)(b * PD + d0 + d) << 7) + t0 + m4) = val;
        }
    } else {
#pragma unroll
        for (int mf = 0; mf < 2; mf++) {
            int row = (tile - 32) * 64 + wm * 32 + mf * 16 + g;
#pragma unroll
            for (int nf = 0; nf < 2; nf++) {
                int col = ntile * 64 + wn * 16 + nf * 8 + tc;
                float b0 = __ldg(bias + col);
                float b1 = __ldg(bias + col + 1);
                float2 o0 = make_float2(acc[mf][nf][0] + b0, acc[mf][nf][1] + b1);
                float2 o1 = make_float2(acc[mf][nf][2] + b0, acc[mf][nf][3] + b1);
                *reinterpret_cast<float2*>(g_Uhb + (size_t)row * PD + col)       = o0;
                *reinterpret_cast<float2*>(g_Uhb + (size_t)(row + 8) * PD + col) = o1;
            }
        }
    }
}

// ---------------------------------------------------------------------------
// Fused scores + softmax + context. Grid (16,16) = 256 CTAs, 256 threads.
// Thread = (t = tid&127, dh = tid>>7).
// Phase A: each thread owns ALL 4 s for its t over half the d-range
//          (d in [dh*16, dh*16+16) of each 32-d chunk). WvT streamed via
//          2-stage cp.async. Partials combined in smem; softmax on dh==0.
// Phase B: v streamed via 2-stage cp.async (16 chunks of 8t x 512f);
//          thread (f4 = t, th = dh) accumulates 4 s over its 4 t per chunk.
// ---------------------------------------------------------------------------
__global__ __launch_bounds__(256) void attn_fused_kernel(
    const float* __restrict__ v, const float* __restrict__ wvec,
    float* __restrict__ u)
{
    const int b = blockIdx.y;
    const int s0 = blockIdx.x * 4;
    const int tid = threadIdx.x;
    const int t = tid & 127;
    const int dh = tid >> 7;

    __shared__ float su[4][PD];          // 4 KB
    __shared__ float sw[PD];             // 1 KB
    __shared__ float rmax[4][4];
    __shared__ float rsum[4][4];
    __shared__ float sbeta[4][PTV];      // 2 KB
    __shared__ float spA[4][PTV];        // 2 KB phase-A partial combine
    __shared__ __align__(16) char sraw[32768];   // staging (2 x 16KB)

    const uint32_t sb_addr = smem_u32(sraw);

    if (tid < PD) sw[tid] = wvec[tid];
    for (int i = tid; i < 4 * PD; i += 256)
        su[i >> 8][i & 255] = g_Uhb[((size_t)(b * PTH + s0 + (i >> 8)) << 8) + (i & 255)];

    // ---- Phase A ----
    const float4* wsrc = reinterpret_cast<const float4*>(g_WvT + ((size_t)b << 15));
    // prologue: chunk 0 (32 d x 128 t = 1024 float4) -> stage 0
#pragma unroll
    for (int j = 0; j < 4; j++)
        cp_async16(sb_addr + (j * 256 + tid) * 16, wsrc + j * 256 + tid);
    CP_COMMIT();

    float a0 = 0.f, a1 = 0.f, a2 = 0.f, a3 = 0.f;
    for (int c = 0; c < 8; c++) {
        const int p = c & 1;
        CP_WAIT(0);
        __syncthreads();           // stage c resident (also publishes su/sw at c=0)
        if (c + 1 < 8) {
            const float4* src = wsrc + (size_t)(c + 1) * 1024;
            uint32_t dst = sb_addr + (p ^ 1) * 16384;
#pragma unroll
            for (int j = 0; j < 4; j++)
                cp_async16(dst + (j * 256 + tid) * 16, src + j * 256 + tid);
        }
        CP_COMMIT();

        const float* wb = reinterpret_cast<const float*>(sraw + p * 16384); // [32][128]
        const int rbase = dh * 16;
        const int dbase = c * 32 + rbase;
#pragma unroll
        for (int j = 0; j < 16; j++) {
            float wv = wb[(rbase + j) * 128 + t];
            float wd = sw[dbase + j];
            a0 += wd * tanh_approx(su[0][dbase + j] + wv);
            a1 += wd * tanh_approx(su[1][dbase + j] + wv);
            a2 += wd * tanh_approx(su[2][dbase + j] + wv);
            a3 += wd * tanh_approx(su[3][dbase + j] + wv);
        }
    }
    __syncthreads();               // last stage reads done

    // combine d-halves
    if (dh == 1) {
        spA[0][t] = a0; spA[1][t] = a1; spA[2][t] = a2; spA[3][t] = a3;
    }
    __syncthreads();

    float e0, e1, e2, e3, i0, i1, i2, i3;
    const int lane = t & 31;
    const int wq = t >> 5;
    if (dh == 0) {
        a0 += spA[0][t]; a1 += spA[1][t]; a2 += spA[2][t]; a3 += spA[3][t];
        float m0 = a0, m1 = a1, m2 = a2, m3 = a3;
#pragma unroll
        for (int off = 16; off; off >>= 1) {
            m0 = fmaxf(m0, __shfl_xor_sync(0xffffffffu, m0, off));
            m1 = fmaxf(m1, __shfl_xor_sync(0xffffffffu, m1, off));
            m2 = fmaxf(m2, __shfl_xor_sync(0xffffffffu, m2, off));
            m3 = fmaxf(m3, __shfl_xor_sync(0xffffffffu, m3, off));
        }
        if (lane == 0) { rmax[0][wq] = m0; rmax[1][wq] = m1; rmax[2][wq] = m2; rmax[3][wq] = m3; }
    }
    __syncthreads();
    if (dh == 0) {
        float m0 = fmaxf(fmaxf(rmax[0][0], rmax[0][1]), fmaxf(rmax[0][2], rmax[0][3]));
        float m1 = fmaxf(fmaxf(rmax[1][0], rmax[1][1]), fmaxf(rmax[1][2], rmax[1][3]));
        float m2 = fmaxf(fmaxf(rmax[2][0], rmax[2][1]), fmaxf(rmax[2][2], rmax[2][3]));
        float m3 = fmaxf(fmaxf(rmax[3][0], rmax[3][1]), fmaxf(rmax[3][2], rmax[3][3]));
        e0 = __expf(a0 - m0); e1 = __expf(a1 - m1);
        e2 = __expf(a2 - m2); e3 = __expf(a3 - m3);
        float s0v = e0, s1v = e1, s2v = e2, s3v = e3;
#pragma unroll
        for (int off = 16; off; off >>= 1) {
            s0v += __shfl_xor_sync(0xffffffffu, s0v, off);
            s1v += __shfl_xor_sync(0xffffffffu, s1v, off);
            s2v += __shfl_xor_sync(0xffffffffu, s2v, off);
            s3v += __shfl_xor_sync(0xffffffffu, s3v, off);
        }
        if (lane == 0) { rsum[0][wq] = s0v; rsum[1][wq] = s1v; rsum[2][wq] = s2v; rsum[3][wq] = s3v; }
    }
    __syncthreads();
    if (dh == 0) {
        i0 = 1.0f / ((rsum[0][0] + rsum[0][1]) + (rsum[0][2] + rsum[0][3]));
        i1 = 1.0f / ((rsum[1][0] + rsum[1][1]) + (rsum[1][2] + rsum[1][3]));
        i2 = 1.0f / ((rsum[2][0] + rsum[2][1]) + (rsum[2][2] + rsum[2][3]));
        i3 = 1.0f / ((rsum[3][0] + rsum[3][1]) + (rsum[3][2] + rsum[3][3]));
        sbeta[0][t] = e0 * i0;
        sbeta[1][t] = e1 * i1;
        sbeta[2][t] = e2 * i2;
        sbeta[3][t] = e3 * i3;
    }
    __syncthreads();

    // ---- Phase B: context ----
    const int f4 = t;              // float4 column 0..127
    const int th = dh;             // t-subgroup within chunk

    const float4* vsrc = reinterpret_cast<const float4*>(v + (size_t)b * PTV * PF);
    // prologue: chunk 0 (8 t x 512 f = 1024 float4) -> stage 0
#pragma unroll
    for (int j = 0; j < 4; j++)
        cp_async16(sb_addr + (j * 256 + tid) * 16, vsrc + j * 256 + tid);
    CP_COMMIT();

    float4 o0 = make_float4(0.f, 0.f, 0.f, 0.f);
    float4 o1 = make_float4(0.f, 0.f, 0.f, 0.f);
    float4 o2 = make_float4(0.f, 0.f, 0.f, 0.f);
    float4 o3 = make_float4(0.f, 0.f, 0.f, 0.f);

    for (int ch = 0; ch < 16; ch++) {
        const int p = ch & 1;
        CP_WAIT(0);
        __syncthreads();
        if (ch + 1 < 16) {
            const float4* src = vsrc + (size_t)(ch + 1) * 1024;
            uint32_t dst = sb_addr + (p ^ 1) * 16384;
#pragma unroll
            for (int j = 0; j < 4; j++)
                cp_async16(dst + (j * 256 + tid) * 16, src + j * 256 + tid);
        }
        CP_COMMIT();

        const float4* vs = reinterpret_cast<const float4*>(sraw + p * 16384); // [8][128]
#pragma unroll
        for (int j = 0; j < 4; j++) {
            int tl = th * 4 + j;
            int tt = ch * 8 + tl;
            float4 vr = vs[tl * 128 + f4];
            float b0 = sbeta[0][tt];
            float b1 = sbeta[1][tt];
            float b2 = sbeta[2][tt];
            float b3 = sbeta[3][tt];
            o0.x += b0 * vr.x; o0.y += b0 * vr.y; o0.z += b0 * vr.z; o0.w += b0 * vr.w;
            o1.x += b1 * vr.x; o1.y += b1 * vr.y; o1.z += b1 * vr.z; o1.w += b1 * vr.w;
            o2.x += b2 * vr.x; o2.y += b2 * vr.y; o2.z += b2 * vr.z; o2.w += b2 * vr.w;
            o3.x += b3 * vr.x; o3.y += b3 * vr.y; o3.z += b3 * vr.z; o3.w += b3 * vr.w;
        }
    }
    __syncthreads();               // staging reads done

    // combine t-halves and store
    float4* spB = reinterpret_cast<float4*>(sraw);   // 4 x 128 float4 = 8KB
    if (th == 1) {
        spB[0 * 128 + f4] = o0;
        spB[1 * 128 + f4] = o1;
        spB[2 * 128 + f4] = o2;
        spB[3 * 128 + f4] = o3;
    }
    __syncthreads();
    if (th == 0) {
        float4 p0 = spB[0 * 128 + f4];
        float4 p1 = spB[1 * 128 + f4];
        float4 p2 = spB[2 * 128 + f4];
        float4 p3 = spB[3 * 128 + f4];
        o0.x += p0.x; o0.y += p0.y; o0.z += p0.z; o0.w += p0.w;
        o1.x += p1.x; o1.y += p1.y; o1.z += p1.z; o1.w += p1.w;
        o2.x += p2.x; o2.y += p2.y; o2.z += p2.z; o2.w += p2.w;
        o3.x += p3.x; o3.y += p3.y; o3.z += p3.z; o3.w += p3.w;
        float* ub = u + (size_t)(b * PTH + s0) * PF + (f4 << 2);
        *reinterpret_cast<float4*>(ub)          = o0;
        *reinterpret_cast<float4*>(ub + PF)     = o1;
        *reinterpret_cast<float4*>(ub + 2 * PF) = o2;
        *reinterpret_cast<float4*>(ub + 3 * PF) = o3;
    }
}

// ---------------------------------------------------------------------------
// kernel_launch
// Inputs: v [16,128,512], h [16,64,512], W [512,256], U [512,256], b [256], w [256,1]
// Output: u [16,64,512] float32
// ---------------------------------------------------------------------------
extern "C" void kernel_launch(void* const* d_in, const int* in_sizes, int n_in,
                              void* d_out, int out_size)
{
    const float* v    = (const float*)d_in[0];
    const float* h    = (const float*)d_in[1];
    const float* W    = (const float*)d_in[2];
    const float* U    = (const float*)d_in[3];
    const float* bvec = (const float*)d_in[4];
    const float* wvec = (const float*)d_in[5];
    float* out = (float*)d_out;

    prep_kernel<<<1024, 256>>>(v, h, W, U);
    mma_gemm_kernel<<<192, 256>>>(bvec);
    attn_fused_kernel<<<dim3(PTH / 4, PB), 256>>>(v, wvec, out);
}